// round 1
// baseline (speedup 1.0000x reference)
#include <cuda_runtime.h>
#include <math.h>

#define Bc 8
#define Nc 1024
#define Mc 20000
#define Cc 80
#define Gc 64
#define NMS_THRf 0.5f
#define EPSf 1e-6f

#define NT 256
#define KI 4           // Nc / NT items per thread
#define NW (NT/32)     // warps per block

// per-batch results: [b*2+0]=push_b, [b*2+1]=pull_b
__device__ float g_partial[Bc * 2];

__device__ __forceinline__ float iou_legacy(float4 a, float4 b, float area_a, float area_b) {
    float lx = fmaxf(a.x, b.x), ly = fmaxf(a.y, b.y);
    float rx = fminf(a.z, b.z), ry = fminf(a.w, b.w);
    float w = fmaxf(rx - lx + 1.0f, 0.0f), h = fmaxf(ry - ly + 1.0f, 0.0f);
    float ov = w * h;
    return ov / (area_a + area_b - ov);
}

__global__ __launch_bounds__(NT, 1)
void nms_loss_kernel(const int* __restrict__ pos_inds,
                     const int* __restrict__ pos_gt_index,
                     const float* __restrict__ gt_bboxes,
                     const float* __restrict__ bbox_preds,
                     const float* __restrict__ cls_scores,
                     const int* __restrict__ gt_labels)
{
    const int b = blockIdx.x;
    const int tid = threadIdx.x;
    const int lane = tid & 31;
    const int wid = tid >> 5;

    __shared__ float4 sbox[Nc];
    __shared__ float  sarea[Nc];
    __shared__ float  sscore[Nc];
    __shared__ int    sgt[Nc];
    __shared__ unsigned char salive[Nc];
    __shared__ float  sgtiou[Gc * Gc];
    __shared__ int    sseen[Gc];
    __shared__ float  w_val[NW];
    __shared__ int    w_idx[NW];
    __shared__ float  w_sum[NW];
    __shared__ int    w_np[NW];
    __shared__ int    w_kill[NW];
    __shared__ int    s_i;
    __shared__ int    s_stop;

    // ---- setup: load boxes, gather scores, compute gt-gt IoU ----
    const float4* bp = (const float4*)(bbox_preds + (size_t)b * Nc * 4);
    for (int n = tid; n < Nc; n += NT) {
        float4 bx = bp[n];
        sbox[n] = bx;
        sarea[n] = (bx.z - bx.x + 1.0f) * (bx.w - bx.y + 1.0f);
        int gi = pos_gt_index[b * Nc + n];
        sgt[n] = gi;
        int lbl = gt_labels[b * Gc + gi];
        int pi = pos_inds[b * Nc + n];
        sscore[n] = cls_scores[((size_t)b * Mc + pi) * Cc + lbl];
        salive[n] = 1;
    }
    const float4* gb = (const float4*)(gt_bboxes + (size_t)b * Gc * 4);
    for (int p = tid; p < Gc * Gc; p += NT) {
        int g1 = p / Gc, g2 = p % Gc;
        float4 a = gb[g1];
        float4 c = gb[g2];
        float a1 = (a.z - a.x + 1.0f) * (a.w - a.y + 1.0f);
        float a2 = (c.z - c.x + 1.0f) * (c.w - c.y + 1.0f);
        sgtiou[p] = iou_legacy(a, c, a1, a2);
    }
    for (int g = tid; g < Gc; g += NT) sseen[g] = -1;
    __syncthreads();

    // thread-0 scalar state (only thread 0's copies are meaningful)
    float tpull = 0.0f, tpush = 0.0f;
    int pcnt = 0, qcnt = 0, cnt = Nc;
    float pull_term = 0.0f;

    for (int step = 0; step < Nc; step++) {
        // ---- Phase A: argmax over alive scores (tie -> lowest index) ----
        float bestv = -1.0f;
        int besti = Nc;
        #pragma unroll
        for (int k = 0; k < KI; k++) {
            int n = tid + k * NT;
            if (salive[n]) {
                float s = sscore[n];
                if (s > bestv || (s == bestv && n < besti)) { bestv = s; besti = n; }
            }
        }
        #pragma unroll
        for (int off = 16; off > 0; off >>= 1) {
            float ov = __shfl_down_sync(0xffffffffu, bestv, off);
            int   oi = __shfl_down_sync(0xffffffffu, besti, off);
            if (ov > bestv || (ov == bestv && oi < besti)) { bestv = ov; besti = oi; }
        }
        if (lane == 0) { w_val[wid] = bestv; w_idx[wid] = besti; }
        __syncthreads();
        if (wid == 0) {
            bestv = (lane < NW) ? w_val[lane] : -1.0f;
            besti = (lane < NW) ? w_idx[lane] : Nc;
            #pragma unroll
            for (int off = NW / 2; off > 0; off >>= 1) {
                float ov = __shfl_down_sync(0xffffffffu, bestv, off);
                int   oi = __shfl_down_sync(0xffffffffu, besti, off);
                if (ov > bestv || (ov == bestv && oi < besti)) { bestv = ov; besti = oi; }
            }
            if (lane == 0) { s_i = besti; s_stop = (bestv < 0.0f) ? 1 : 0; }
        }
        __syncthreads();
        if (s_stop) break;

        const int i = s_i;
        const int g = sgt[i];
        const float4 bi = sbox[i];
        const float ai = sarea[i];

        // ---- Phase B: pull / seen bookkeeping (thread 0 only touches sseen) ----
        if (tid == 0) {
            int prev = sseen[g];
            if (prev >= 0) {
                float iou_pi = iou_legacy(sbox[prev], bi, sarea[prev], ai);
                float ms = fmaxf(iou_pi, EPSf);
                pull_term = -logf(1.0f - NMS_THRf + ms) * sscore[i];
                pcnt++;                 // counted even if this is the last pop
            } else {
                sseen[g] = i;
                pull_term = 0.0f;
            }
        }

        // ---- Phase C: row IoU vs popped box, push terms, suppression ----
        float lsum = 0.0f;
        int lnp = 0, lkill = 0;
        #pragma unroll
        for (int k = 0; k < KI; k++) {
            int n = tid + k * NT;
            if (n == i) {
                salive[n] = 0;          // pop i (not counted in lkill)
            } else if (salive[n]) {
                float4 bn = sbox[n];
                float iouv = iou_legacy(bi, bn, ai, sarea[n]);
                if (iouv > NMS_THRf) {
                    salive[n] = 0;
                    lkill++;
                    int gn = sgt[n];
                    if (gn != g && iouv > sgtiou[g * Gc + gn]) {
                        lnp++;
                        lsum += -logf(1.0f - iouv) * sscore[n];
                    }
                }
            }
        }
        #pragma unroll
        for (int off = 16; off > 0; off >>= 1) {
            lsum  += __shfl_down_sync(0xffffffffu, lsum, off);
            lnp   += __shfl_down_sync(0xffffffffu, lnp, off);
            lkill += __shfl_down_sync(0xffffffffu, lkill, off);
        }
        if (lane == 0) { w_sum[wid] = lsum; w_np[wid] = lnp; w_kill[wid] = lkill; }
        __syncthreads();
        if (tid == 0) {
            float tsum = 0.0f;
            int tnp = 0, tkill = 0;
            #pragma unroll
            for (int wv = 0; wv < NW; wv++) {
                tsum += w_sum[wv]; tnp += w_np[wv]; tkill += w_kill[wv];
            }
            bool remaining = (cnt - 1) > 0;   // anything alive after popping i?
            if (remaining) {
                tpull += pull_term;
                if (tnp > 0) { tpush += tsum / (float)tnp; qcnt += tnp; }
            }
            cnt -= 1 + tkill;
        }
        __syncthreads();   // publish alive[] updates + keep loop in lockstep
    }

    if (tid == 0) {
        g_partial[b * 2 + 0] = tpush / ((float)qcnt + EPSf);
        g_partial[b * 2 + 1] = tpull / ((float)pcnt + EPSf);
    }
}

__global__ void finalize_kernel(float* out) {
    float sp = 0.0f, sl = 0.0f;
    for (int b = 0; b < Bc; b++) {
        sp += g_partial[b * 2 + 0];
        sl += g_partial[b * 2 + 1];
    }
    out[0] = sp / (float)Bc;   // mean(push) * PUSH_W
    out[1] = sl / (float)Bc;   // mean(pull) * PULL_W
}

extern "C" void kernel_launch(void* const* d_in, const int* in_sizes, int n_in,
                              void* d_out, int out_size) {
    const int*   pos_inds     = (const int*)d_in[0];
    const int*   pos_gt_index = (const int*)d_in[1];
    const float* gt_bboxes    = (const float*)d_in[2];
    const float* bbox_preds   = (const float*)d_in[3];
    const float* cls_scores   = (const float*)d_in[4];
    const int*   gt_labels    = (const int*)d_in[5];
    float* out = (float*)d_out;

    nms_loss_kernel<<<Bc, NT>>>(pos_inds, pos_gt_index, gt_bboxes,
                                bbox_preds, cls_scores, gt_labels);
    finalize_kernel<<<1, 1>>>(out);
}